// round 16
// baseline (speedup 1.0000x reference)
#include <cuda_runtime.h>
#include <cuda_bf16.h>
#include <math.h>
#include <cstdint>

// ---------------- problem constants ----------------
#define C_IN 576
#define HF   12
#define WF   20
#define NB   16
#define POS  240
#define M_TOT 3840                 // positions (16*240)
#define G_TOT 4608                 // 8*576 output channels
#define TY_T 3                     // winograd F(4,3) tile rows  (12/4)
#define TX_T 5                     // winograd F(4,3) tile cols  (20/4)
#define NT   15                    // tiles per image
#define J_TOT (NB*NT)              // 240
#define J_PAD 256
#define NUV  36                    // 6x6 transform plane count
#define KC   32                    // k per chunk
#define NCH  (C_IN/KC)             // 18 chunks

// ---------------- scratch (static device globals; zero-initialized) ----------------
__device__ __align__(16) __nv_bfloat16 g_Uh[(size_t)NUV * G_TOT * C_IN];  // ~191MB
__device__ __align__(16) __nv_bfloat16 g_Ul[(size_t)NUV * G_TOT * C_IN];  // ~191MB
__device__ __align__(16) __nv_bfloat16 g_Vh[(size_t)NUV * J_PAD * C_IN];  // ~10.6MB (pad rows stay 0)
__device__ __align__(16) __nv_bfloat16 g_Vl[(size_t)NUV * J_PAD * C_IN];
__device__ __align__(16) float g_M[(size_t)NUV * G_TOT * J_PAD];          // ~170MB
__device__ __align__(16) float g_H[(size_t)G_TOT * M_TOT];                // ~71MB
__device__ float g_scale[G_TOT];
__device__ float g_shift[G_TOT];
__device__ __align__(16) float g_maps[14 * M_TOT];
__device__ __align__(16) float g_cand[NB * 100 * 10];

// ---------------- helpers ----------------
__device__ __forceinline__ float sigm(float x) { return 1.0f / (1.0f + expf(-x)); }
__device__ __forceinline__ float clipf(float x, float lo, float hi) { return fminf(fmaxf(x, lo), hi); }

__device__ __forceinline__ void bf16_split(float x, __nv_bfloat16& hi, __nv_bfloat16& lo) {
    hi = __float2bfloat16_rn(x);
    lo = __float2bfloat16_rn(x - __bfloat162float(hi));
}

// bf16 m16n8k16 mma, fp32 accumulate
__device__ __forceinline__ void mma_bf16(float* c, const uint32_t* a, uint32_t b0, uint32_t b1) {
    asm volatile(
        "mma.sync.aligned.m16n8k16.row.col.f32.bf16.bf16.f32 "
        "{%0,%1,%2,%3}, {%4,%5,%6,%7}, {%8,%9}, {%0,%1,%2,%3};"
        : "+f"(c[0]), "+f"(c[1]), "+f"(c[2]), "+f"(c[3])
        : "r"(a[0]), "r"(a[1]), "r"(a[2]), "r"(a[3]), "r"(b0), "r"(b1));
}

__device__ __forceinline__ void ldmatrix_x4(uint32_t* r, uint32_t addr) {
    asm volatile("ldmatrix.sync.aligned.m8n8.x4.shared.b16 {%0,%1,%2,%3}, [%4];"
        : "=r"(r[0]), "=r"(r[1]), "=r"(r[2]), "=r"(r[3]) : "r"(addr));
}

__device__ __forceinline__ void cp_async16(uint32_t dst, const void* src) {
    asm volatile("cp.async.cg.shared.global [%0], [%1], 16;" :: "r"(dst), "l"(src));
}

// ---------------- kernel: BN fold ----------------
__global__ void bn_prep_kernel(const float* __restrict__ g, const float* __restrict__ b,
                               const float* __restrict__ m, const float* __restrict__ v) {
    int i = blockIdx.x * blockDim.x + threadIdx.x;
    if (i < G_TOT) {
        float sc = g[i] / sqrtf(v[i] + 1e-5f);
        g_scale[i] = sc;
        g_shift[i] = b[i] - m[i] * sc;
    }
}

// F(4,3) G-row combo applied to a 3-vector (a,b,c) -> 6 outputs
#define GCOMBO(out, a, b, c) \
    out[0] = 0.25f * (a); \
    out[1] = -(1.0f/6.0f) * ((a) + (b) + (c)); \
    out[2] = (1.0f/6.0f) * (-(a) + (b) - (c)); \
    out[3] = (1.0f/24.0f) * (a) + (1.0f/12.0f) * (b) + (1.0f/6.0f) * (c); \
    out[4] = (1.0f/24.0f) * (a) - (1.0f/12.0f) * (b) + (1.0f/6.0f) * (c); \
    out[5] = (c);

// ---------------- kernel: winograd F(4,3) weight transform -> split bf16 (2 ci/thread) ----------------
__global__ void wg_transform_kernel(const float* __restrict__ w1) {
    int idx = blockIdx.x * blockDim.x + threadIdx.x;      // 4608 * 288
    int co = idx / (C_IN / 2), p = idx % (C_IN / 2);
    int ci = 2 * p;
    const float* w = w1 + ((size_t)co * C_IN + ci) * 9;   // 18 contiguous floats
    float U2[2][36];
#pragma unroll
    for (int q = 0; q < 2; q++) {
        const float* wq = w + q * 9;
        float T[6][3];
        float col[6];
#pragma unroll
        for (int c = 0; c < 3; c++) {
            GCOMBO(col, wq[c], wq[3 + c], wq[6 + c]);
#pragma unroll
            for (int r = 0; r < 6; r++) T[r][c] = col[r];
        }
#pragma unroll
        for (int r = 0; r < 6; r++) {
            float u[6];
            GCOMBO(u, T[r][0], T[r][1], T[r][2]);
#pragma unroll
            for (int c = 0; c < 6; c++) U2[q][r * 6 + c] = u[c];
        }
    }
    size_t plane = (size_t)G_TOT * C_IN;
    size_t off0 = (size_t)co * C_IN + ci;
#pragma unroll
    for (int uv = 0; uv < 36; uv++) {
        __nv_bfloat16 h0, l0, h1, l1;
        bf16_split(U2[0][uv], h0, l0);
        bf16_split(U2[1][uv], h1, l1);
        __nv_bfloat162 hv; hv.x = h0; hv.y = h1;
        __nv_bfloat162 lv; lv.x = l0; lv.y = l1;
        *reinterpret_cast<__nv_bfloat162*>(g_Uh + uv * plane + off0) = hv;
        *reinterpret_cast<__nv_bfloat162*>(g_Ul + uv * plane + off0) = lv;
    }
}

// F(4,3) B^T-row combo applied to a 6-vector -> 6 outputs
#define BCOMBO(out, x0, x1, x2, x3, x4, x5) \
    out[0] = 4.0f*(x0) - 5.0f*(x2) + (x4); \
    out[1] = -4.0f*(x1) - 4.0f*(x2) + (x3) + (x4); \
    out[2] =  4.0f*(x1) - 4.0f*(x2) - (x3) + (x4); \
    out[3] = -2.0f*(x1) - (x2) + 2.0f*(x3) + (x4); \
    out[4] =  2.0f*(x1) - (x2) - 2.0f*(x3) + (x4); \
    out[5] =  4.0f*(x1) - 5.0f*(x3) + (x5);

// ---------------- kernel: winograd input transform -> split bf16 [uv][j][ci] ----------------
__global__ void in_transform_kernel(const float* __restrict__ f) {
    int idx = blockIdx.x * blockDim.x + threadIdx.x;      // (16*15)*576, ci fastest
    if (idx >= NB * NT * C_IN) return;
    int j  = idx / C_IN;                                  // n*NT + t
    int ci = idx % C_IN;
    int n = j / NT, t = j % NT;
    int ty = t / TX_T, tx = t % TX_T;
    const float* fp = f + ((size_t)n * C_IN + ci) * POS;
    float X[6][6];
#pragma unroll
    for (int a = 0; a < 6; a++) {
        int iy = 4 * ty - 1 + a;
#pragma unroll
        for (int b = 0; b < 6; b++) {
            int ix = 4 * tx - 1 + b;
            X[a][b] = ((unsigned)iy < HF && (unsigned)ix < WF) ? fp[iy * WF + ix] : 0.f;
        }
    }
    float T[6][6];
    {
        float col[6];
#pragma unroll
        for (int b = 0; b < 6; b++) {
            BCOMBO(col, X[0][b], X[1][b], X[2][b], X[3][b], X[4][b], X[5][b]);
#pragma unroll
            for (int a = 0; a < 6; a++) T[a][b] = col[a];
        }
    }
    size_t base = (size_t)j * C_IN + ci;
    size_t plane = (size_t)J_PAD * C_IN;
#pragma unroll
    for (int a = 0; a < 6; a++) {
        float v[6];
        BCOMBO(v, T[a][0], T[a][1], T[a][2], T[a][3], T[a][4], T[a][5]);
#pragma unroll
        for (int b = 0; b < 6; b++) {
            __nv_bfloat16 hi, lo;
            bf16_split(v[b], hi, lo);
            size_t off = (size_t)(a * 6 + b) * plane + base;
            g_Vh[off] = hi;
            g_Vl[off] = lo;
        }
    }
}

// ---------------- tensor-core GEMM: bf16 3-term split, M_uv = U_uv x V_uv ----------------
// grid (36, 36): CTA tile 128co x 256j (full J), 512 threads = 16 warps (4m x 4n),
// warp tile 32co x 64j. 3-stage cp.async pipeline, one barrier per chunk.
// Stage layout: [Uh 128x80][Ul 128x80][Vh 256x80][Vl 256x80] = 61440 B.
#define U_TB   10240
#define V_TB   20480
#define STAGE_B 61440
#define GEMM_SMEM (3*STAGE_B)

__global__ __launch_bounds__(512, 1) void gemm_mma_kernel() {
    extern __shared__ char smem[];
    const uint32_t sbase = (uint32_t)__cvta_generic_to_shared(smem);
    const int tid = threadIdx.x;
    const int wid = tid >> 5, lane = tid & 31;
    const int g = lane >> 2, tg = lane & 3;
    const int gb = blockIdx.x * 128;
    const int uv = blockIdx.y;
    const int wm = (wid & 3) * 32;            // warp co base within tile
    const int wn = (wid >> 2) * 64;           // warp j  base within tile

    const char* srcU[2];
    srcU[0] = (const char*)(g_Uh + ((size_t)uv * G_TOT + gb) * C_IN);
    srcU[1] = (const char*)(g_Ul + ((size_t)uv * G_TOT + gb) * C_IN);
    const char* srcV[2];
    srcV[0] = (const char*)(g_Vh + (size_t)uv * J_PAD * C_IN);
    srcV[1] = (const char*)(g_Vl + (size_t)uv * J_PAD * C_IN);

    const int sr = tid >> 2;                  // 0..127
    const int ss = tid & 3;                   // chunk 0..3 (16B each)

    // ldmatrix lane address components
    const int q = lane >> 3;
    const int a_row = (lane & 7) + ((q & 1) << 3);     // rows 0..15
    const int a_byte = (q >> 1) << 4;                  // 0 or 16
    const int b_row = lane & 7;
    const int b_byte = (q & 1) << 4;                   // 0 or 16
    const int b_sel = q >> 1;                          // which nt of the pair

    // stage chunk c into buffer buf: U 1 op/thread/array, V 2 ops/thread/array
    auto stage = [&](int c, int buf) {
        uint32_t bs = sbase + buf * STAGE_B;
        const size_t gstep = (size_t)C_IN * 2;
        const size_t koff = (size_t)c * (KC * 2) + ss * 16;
#pragma unroll
        for (int u = 0; u < 2; u++)
            cp_async16(bs + u * U_TB + sr * 80 + ss * 16, srcU[u] + (size_t)sr * gstep + koff);
#pragma unroll
        for (int u = 0; u < 2; u++) {
            uint32_t vb = bs + 2 * U_TB + u * V_TB;
            cp_async16(vb + sr * 80 + ss * 16,          srcV[u] + (size_t)sr * gstep + koff);
            cp_async16(vb + (sr + 128) * 80 + ss * 16,  srcV[u] + (size_t)(sr + 128) * gstep + koff);
        }
        asm volatile("cp.async.commit_group;" ::: "memory");
    };

    stage(0, 0);
    stage(1, 1);

    float acc[2][8][4];
#pragma unroll
    for (int mt = 0; mt < 2; mt++)
#pragma unroll
        for (int nt = 0; nt < 8; nt++)
#pragma unroll
            for (int i = 0; i < 4; i++) acc[mt][nt][i] = 0.f;

    for (int c = 0; c < NCH; c++) {
        const int buf = c % 3;
        asm volatile("cp.async.wait_group 1;" ::: "memory");
        __syncthreads();
        if (c + 2 < NCH) stage(c + 2, (c + 2) % 3);

        const uint32_t Us = sbase + buf * STAGE_B;
        const uint32_t Vs = Us + 2 * U_TB;
#pragma unroll
        for (int kh = 0; kh < 2; kh++) {
            uint32_t ah[2][4], al[2][4];
#pragma unroll
            for (int mt = 0; mt < 2; mt++) {
                uint32_t abase = Us + (wm + mt * 16 + a_row) * 80 + kh * 32 + a_byte;
                ldmatrix_x4(ah[mt], abase);
                ldmatrix_x4(al[mt], abase + U_TB);
            }
#pragma unroll
            for (int pr = 0; pr < 4; pr++) {
                uint32_t bbase = Vs + (wn + (2 * pr + b_sel) * 8 + b_row) * 80 + kh * 32 + b_byte;
                uint32_t bh[4], bl[4];
                ldmatrix_x4(bh, bbase);
                ldmatrix_x4(bl, bbase + V_TB);
#pragma unroll
                for (int half = 0; half < 2; half++) {
                    const int nt = 2 * pr + half;
                    uint32_t h0 = bh[2 * half], h1 = bh[2 * half + 1];
                    uint32_t l0 = bl[2 * half], l1 = bl[2 * half + 1];
#pragma unroll
                    for (int mt = 0; mt < 2; mt++) {
                        mma_bf16(acc[mt][nt], ah[mt], h0, h1);
                        mma_bf16(acc[mt][nt], ah[mt], l0, l1);
                        mma_bf16(acc[mt][nt], al[mt], h0, h1);
                    }
                }
            }
        }
    }

    // epilogue: store fp32 to g_M[uv][co][j]
    float* Mbase = g_M + (size_t)uv * G_TOT * J_PAD;
#pragma unroll
    for (int mt = 0; mt < 2; mt++) {
        const int row = gb + wm + mt * 16 + g;
#pragma unroll
        for (int nt = 0; nt < 8; nt++) {
            const int j0 = wn + nt * 8 + 2 * tg;
            *(float2*)(Mbase + (size_t)row * J_PAD + j0)       = make_float2(acc[mt][nt][0], acc[mt][nt][1]);
            *(float2*)(Mbase + (size_t)(row + 8) * J_PAD + j0) = make_float2(acc[mt][nt][2], acc[mt][nt][3]);
        }
    }
}

// F(4,3) A^T-row combo applied to a 6-vector -> 4 outputs
#define ACOMBO(out, x0, x1, x2, x3, x4, x5) \
    out[0] = (x0) + (x1) + (x2) + (x3) + (x4); \
    out[1] = (x1) - (x2) + 2.0f*(x3) - 2.0f*(x4); \
    out[2] = (x1) + (x2) + 4.0f*(x3) + 4.0f*(x4); \
    out[3] = (x1) - (x2) + 8.0f*(x3) - 8.0f*(x4) + (x5);

// ---------------- kernel: inverse transform + BN + SiLU -> g_H[co][m] ----------------
__global__ void out_transform_kernel() {
    int idx = blockIdx.x * blockDim.x + threadIdx.x;      // 4608*240
    if (idx >= G_TOT * J_TOT) return;
    int co = idx / J_TOT, j = idx % J_TOT;
    int n = j / NT, t = j % NT;
    int ty = t / TX_T, tx = t % TX_T;
    size_t plane = (size_t)G_TOT * J_PAD;
    const float* mp = g_M + (size_t)co * J_PAD + j;
    float M[6][6];
#pragma unroll
    for (int uv = 0; uv < 36; uv++) M[uv / 6][uv % 6] = mp[(size_t)uv * plane];
    float T[4][6];
    {
        float col[4];
#pragma unroll
        for (int b = 0; b < 6; b++) {
            ACOMBO(col, M[0][b], M[1][b], M[2][b], M[3][b], M[4][b], M[5][b]);
#pragma unroll
            for (int a = 0; a < 4; a++) T[a][b] = col[a];
        }
    }
    const float sc = g_scale[co], sh = g_shift[co];
    float* hp = g_H + (size_t)co * M_TOT + n * POS + (4 * ty) * WF + 4 * tx;
#pragma unroll
    for (int a = 0; a < 4; a++) {
        float y[4];
        ACOMBO(y, T[a][0], T[a][1], T[a][2], T[a][3], T[a][4], T[a][5]);
        float4 o;
        float v;
        v = y[0] * sc + sh; o.x = v / (1.0f + expf(-v));
        v = y[1] * sc + sh; o.y = v / (1.0f + expf(-v));
        v = y[2] * sc + sh; o.z = v / (1.0f + expf(-v));
        v = y[3] * sc + sh; o.w = v / (1.0f + expf(-v));
        *(float4*)(hp + a * WF) = o;
    }
}

// ---------------- kernel 1: global-average pool + linear + single_out ----------------
__global__ void single_kernel(const float* __restrict__ f,
                              const float* __restrict__ linW,
                              const float* __restrict__ linb,
                              float* __restrict__ out) {
    const int n = blockIdx.x;
    const int c = threadIdx.x;                 // 576
    __shared__ float sf1[C_IN];
    __shared__ float slin[10];
    const float* p = f + ((size_t)n * C_IN + c) * POS;
    float s = 0.f;
#pragma unroll 4
    for (int i = 0; i < POS; i++) s += p[i];
    sf1[c] = s / 240.0f;
    __syncthreads();
    if (c < 10) {
        float a = linb[c];
        for (int k = 0; k < C_IN; k++) a += sf1[k] * linW[c * C_IN + k];
        slin[c] = a;
    }
    __syncthreads();
    if (c == 0) {
        const float eps = 1e-5f;
        float conf = clipf(sigm(slin[0]), eps, 1.0f - eps);
        int best = 0; float bv = slin[1];
        for (int i = 1; i < 5; i++) if (slin[1 + i] > bv) { bv = slin[1 + i]; best = i; }
        float dist = sigm(slin[6]) * 3.0f;
        float offv = tanhf(slin[7]);
        float sev  = clipf(sigm(slin[8]), eps, 1.0f - eps);
        float surf = clipf(sigm(slin[9]), eps, 1.0f - eps);
        float* o = out + n * 6;
        o[0] = conf; o[1] = (float)best; o[2] = dist; o[3] = offv; o[4] = sev; o[5] = surf;
    }
}

// ---------------- kernel 5: w2 reduction -> 14 maps ----------------
__constant__ int c_offs[9] = {0, 5, 6, 8, 10, 11, 12, 13, 14};
__global__ void maps_kernel(const float* __restrict__ w2, const float* __restrict__ b2) {
    const int head = blockIdx.y;
    const int o0 = c_offs[head], o1 = c_offs[head + 1];
    const int no = o1 - o0;
    __shared__ float sw2[5][C_IN];
    const int t = threadIdx.x;                 // 128
    for (int i = t; i < no * C_IN; i += 128) sw2[i / C_IN][i % C_IN] = w2[o0 * C_IN + i];
    __syncthreads();
    const int m = blockIdx.x * 128 + t;
    float acc[5] = {0.f, 0.f, 0.f, 0.f, 0.f};
    const float* hp = g_H + (size_t)head * C_IN * M_TOT + m;
#pragma unroll 4
    for (int c = 0; c < C_IN; c++) {
        float v = hp[(size_t)c * M_TOT];
#pragma unroll
        for (int o = 0; o < 5; o++)
            if (o < no) acc[o] += sw2[o][c] * v;
    }
#pragma unroll
    for (int o = 0; o < 5; o++)
        if (o < no) g_maps[(o0 + o) * M_TOT + m] = acc[o] + b2[o0 + o];
}

// ---------------- kernel 6: per-(n,class) top-20 ----------------
__global__ void topk_kernel() {
    const int n = blockIdx.x / 5, j = blockIdx.x % 5;
    const int t = threadIdx.x;                 // 256
    __shared__ float sc[256];
    __shared__ float rv[256];
    __shared__ int   ri[256];
    __shared__ float selv[20];
    __shared__ int   seli[20];

    float s = -1e30f;
    if (t < POS) {
        float heat = sigm(g_maps[j * M_TOT + n * POS + t]);
        float cf   = sigm(g_maps[5 * M_TOT + n * POS + t]);
        s = heat * cf;
    }
    sc[t] = s;
    __syncthreads();

    for (int r = 0; r < 20; r++) {
        rv[t] = sc[t]; ri[t] = t;
        __syncthreads();
#pragma unroll
        for (int off = 128; off > 0; off >>= 1) {
            if (t < off) {
                float v2 = rv[t + off]; int i2 = ri[t + off];
                if (v2 > rv[t] || (v2 == rv[t] && i2 < ri[t])) { rv[t] = v2; ri[t] = i2; }
            }
            __syncthreads();
        }
        if (t == 0) { selv[r] = rv[0]; seli[r] = ri[0]; sc[ri[0]] = -1e30f; }
        __syncthreads();
    }

    if (t < 20) {
        const int idx = seli[t];
        const float score = selv[t];
        const int base = n * POS + idx;
        float gx = sigm(g_maps[6  * M_TOT + base]);
        float gy = sigm(g_maps[7  * M_TOT + base]);
        float gw = sigm(g_maps[8  * M_TOT + base]);
        float gh = sigm(g_maps[9  * M_TOT + base]);
        float gd = sigm(g_maps[10 * M_TOT + base]) * 3.0f;
        float go = tanhf(g_maps[11 * M_TOT + base]);
        float gs = sigm(g_maps[12 * M_TOT + base]);
        float gf = sigm(g_maps[13 * M_TOT + base]);
        float xi = (float)(idx % WF);
        float yi = (float)(idx / WF);
        float cx = clipf(xi + gx, 0.f, (float)(WF - 1)) * 32.0f;
        float cy = clipf(yi + gy, 0.f, (float)(HF - 1)) * 32.0f;
        float bw = clipf(gw, 0.f, 1.f) * 640.0f;
        float bh = clipf(gh, 0.f, 1.f) * 384.0f;
        float x1 = clipf(cx - bw * 0.5f, 0.f, 639.0f);
        float y1 = clipf(cy - bh * 0.5f, 0.f, 383.0f);
        float x2 = clipf(cx + bw * 0.5f, 0.f, 639.0f);
        float y2 = clipf(cy + bh * 0.5f, 0.f, 383.0f);
        float* row = g_cand + ((size_t)n * 100 + j * 20 + t) * 10;
        row[0] = score; row[1] = (float)j; row[2] = gd; row[3] = go; row[4] = gs;
        row[5] = gf; row[6] = x1; row[7] = y1; row[8] = x2; row[9] = y2;
    }
}

// ---------------- kernel 7: stable sort by dist -> dets_out ----------------
__global__ void sort_out_kernel(float* __restrict__ out) {
    const int n = blockIdx.x;
    const int t = threadIdx.x;                 // 128
    __shared__ float d[100];
    if (t < 100) d[t] = g_cand[((size_t)n * 100 + t) * 10 + 2];
    __syncthreads();
    if (t < 100) {
        float di = d[t];
        int rank = 0;
        for (int k = 0; k < 100; k++) {
            float dk = d[k];
            rank += (dk < di) || (dk == di && k < t);
        }
        if (rank < 20) {
            float* dst = out + 96 + ((size_t)n * 20 + rank) * 10;
            const float* src = g_cand + ((size_t)n * 100 + t) * 10;
#pragma unroll
            for (int q = 0; q < 10; q++) dst[q] = src[q];
        }
    }
}

// ---------------- launch ----------------
extern "C" void kernel_launch(void* const* d_in, const int* in_sizes, int n_in,
                              void* d_out, int out_size) {
    const float* f    = (const float*)d_in[0];
    const float* w1   = (const float*)d_in[1];
    const float* bng  = (const float*)d_in[2];
    const float* bnb  = (const float*)d_in[3];
    const float* bnm  = (const float*)d_in[4];
    const float* bnv  = (const float*)d_in[5];
    const float* w2   = (const float*)d_in[6];
    const float* b2   = (const float*)d_in[7];
    const float* linW = (const float*)d_in[8];
    const float* linb = (const float*)d_in[9];
    float* out = (float*)d_out;

    cudaFuncSetAttribute(gemm_mma_kernel, cudaFuncAttributeMaxDynamicSharedMemorySize, GEMM_SMEM);

    single_kernel<<<NB, C_IN>>>(f, linW, linb, out);
    bn_prep_kernel<<<(G_TOT + 255) / 256, 256>>>(bng, bnb, bnm, bnv);
    wg_transform_kernel<<<(G_TOT * (C_IN / 2)) / 256, 256>>>(w1);         // 5184 blocks
    in_transform_kernel<<<(NB * NT * C_IN + 255) / 256, 256>>>(f);        // 540 blocks
    dim3 gg(G_TOT / 128, NUV);                                            // (36, 36)
    gemm_mma_kernel<<<gg, 512, GEMM_SMEM>>>();
    out_transform_kernel<<<(G_TOT * J_TOT + 255) / 256, 256>>>();         // 4320 blocks
    dim3 mg(M_TOT / 128, 8);
    maps_kernel<<<mg, 128>>>(w2, b2);
    topk_kernel<<<NB * 5, 256>>>();
    sort_out_kernel<<<NB, 128>>>(out);
}